// round 9
// baseline (speedup 1.0000x reference)
#include <cuda_runtime.h>
#include <cstdint>

#define BB 64
#define CC 4096
#define IND 512
#define OO 16
#define TI 16                 // i-tile
#define NTILES (IND / TI)     // 32
#define NCAPW 2               // capsules per WARP
#define WARPS 4
#define NTH (32 * WARPS)
#define CAPS_CTA (NCAPW * WARPS)   // 8
#define BH 32                 // b-rows per CTA (page-set fix)
#define PIPE 3

#define XCAP 512              // 32 rows x 16 words per capsule per stage
#define WCAP 256              // 16 rows x 16 words per capsule per stage
#define XWARP (NCAPW * XCAP)  // 1024 floats
#define WWARP (NCAPW * WCAP)  // 512 floats
#define STG (XWARP + WWARP)   // 1536 floats per warp-stage
#define SMEM_FLOATS (PIPE * WARPS * STG)   // 18432 floats = 72 KB

// chunk swizzle: logical 16B chunk j of row r lives at position sigma(r,j)
__device__ __forceinline__ int sig(int r, int j) {
    return (j + ((r >> 1) & 3)) & 3;
}

// ---- packed f32x2 helpers ----
__device__ __forceinline__ uint64_t pack_dup(float x) {
    uint64_t r;
    asm("mov.b64 %0, {%1, %1};" : "=l"(r) : "f"(x));
    return r;
}
__device__ __forceinline__ void fma2(uint64_t& d, uint64_t a, uint64_t b) {
    asm("fma.rn.f32x2 %0, %1, %2, %0;" : "+l"(d) : "l"(a), "l"(b));
}
__device__ __forceinline__ void unpack2(uint64_t v, float& lo, float& hi) {
    asm("mov.b64 {%0, %1}, %2;" : "=f"(lo), "=f"(hi) : "l"(v));
}

// ---- cp.async 16B, L1-bypass ----
__device__ __forceinline__ void cp16(void* dst_smem, const void* src) {
    uint32_t d = (uint32_t)__cvta_generic_to_shared(dst_smem);
    asm volatile("cp.async.cg.shared.global [%0], [%1], 16;"
                 :: "r"(d), "l"(src) : "memory");
}
__device__ __forceinline__ void cp_commit() {
    asm volatile("cp.async.commit_group;" ::: "memory");
}
__device__ __forceinline__ void cp_wait2() {
    asm volatile("cp.async.wait_group 2;" ::: "memory");
}
__device__ __forceinline__ void cp_wait1() {
    asm volatile("cp.async.wait_group 1;" ::: "memory");
}
__device__ __forceinline__ void cp_wait0() {
    asm volatile("cp.async.wait_group 0;" ::: "memory");
}

extern __shared__ float sm[];

__global__ __launch_bounds__(NTH)
void primarycaps_kernel(const float* __restrict__ x,
                        const float* __restrict__ W,
                        const float* __restrict__ bias,
                        float* __restrict__ out)
{
    const int t    = threadIdx.x;
    const int wid  = t >> 5;
    const int lane = t & 31;

    const int c0 = blockIdx.x * CAPS_CTA + wid * NCAPW;  // this warp's 2 caps
    const int b0 = blockIdx.y * BH;                      // this CTA's b-half

    // compute map (within warp)
    const int tb  = lane & 7;         // b-group: owns rows tb + 8k (k=0..3)
    const int to  = (lane >> 3) & 1;  // o-half
    const int cap = lane >> 4;        // capsule within warp

    // staging map: lane -> (row base, 16B chunk); one instr = 8 rows x 64B
    const int sr = (lane >> 2) & 7;
    const int sj = lane & 3;

    // per-warp smem stage bases
    float* stg[PIPE];
    #pragma unroll
    for (int s = 0; s < PIPE; ++s)
        stg[s] = sm + (s * WARPS + wid) * STG;

    // ---- accumulators: 4 b-rows x 4 o-pairs (packed f32x2) ----
    uint64_t acc[4][4];
    #pragma unroll
    for (int k = 0; k < 4; ++k)
        #pragma unroll
        for (int j = 0; j < 4; ++j)
            acc[k][j] = 0ULL;

    // ---- stage helper: tile jt into buffer bf (this warp only) ----
    auto stage = [&](int bf, int jt) {
        float* dx = stg[bf];           // x at +0, W at +XWARP
        #pragma unroll
        for (int cc = 0; cc < NCAPW; ++cc) {
            #pragma unroll
            for (int k = 0; k < 4; ++k) {
                const int row = sr + 8 * k;
                cp16(&dx[cc * XCAP + row * 16 + sig(row, sj) * 4],
                     x + ((size_t)(b0 + row) * CC + c0 + cc) * IND
                       + (size_t)jt * TI + sj * 4);
            }
        }
        float* dw = stg[bf] + XWARP;
        #pragma unroll
        for (int cc = 0; cc < NCAPW; ++cc) {
            #pragma unroll
            for (int m = 0; m < 2; ++m) {
                const int i = sr + 8 * m;
                cp16(&dw[cc * WCAP + i * 16 + sig(i, sj) * 4],
                     W + (((size_t)(c0 + cc)) * IND + (size_t)jt * TI + i) * OO
                       + sj * 4);
            }
        }
        cp_commit();
    };

    // ---- prologue: 2 stages in flight ----
    stage(0, 0);
    stage(1, 1);

    int bj = 0;                        // j % PIPE
    for (int j = 0; j < NTILES; ++j) {
        // issue stage j+2 into buffer (j+2)%3 (== (j-1)%3, freed last iter)
        if (j + 2 < NTILES) {
            int bs = bj + 2; if (bs >= PIPE) bs -= PIPE;
            stage(bs, j + 2);
        }
        // wait for tile j's group
        if (j < NTILES - 2)       cp_wait2();
        else if (j == NTILES - 2) cp_wait1();
        else                      cp_wait0();
        __syncwarp();

        // ---- compute tile j ----
        const float* __restrict__ xb = stg[bj] + cap * XCAP;
        const float* __restrict__ wb = stg[bj] + XWARP + cap * WCAP;

        #pragma unroll
        for (int q = 0; q < 4; ++q) {           // 4-i blocks
            float4 xv[4];
            #pragma unroll
            for (int k = 0; k < 4; ++k) {
                const int row = tb + 8 * k;
                xv[k] = *(const float4*)&xb[row * 16 + sig(row, q) * 4];
            }

            #pragma unroll
            for (int r = 0; r < 4; ++r) {
                const int i = q * 4 + r;
                const ulonglong2 wA =
                    *(const ulonglong2*)&wb[i * 16 + sig(i, 2 * to) * 4];
                const ulonglong2 wB =
                    *(const ulonglong2*)&wb[i * 16 + sig(i, 2 * to + 1) * 4];

                #pragma unroll
                for (int k = 0; k < 4; ++k) {
                    const float xs = (r == 0) ? xv[k].x :
                                     (r == 1) ? xv[k].y :
                                     (r == 2) ? xv[k].z : xv[k].w;
                    const uint64_t xd = pack_dup(xs);
                    fma2(acc[k][0], xd, wA.x);
                    fma2(acc[k][1], xd, wA.y);
                    fma2(acc[k][2], xd, wB.x);
                    fma2(acc[k][3], xd, wB.y);
                }
            }
        }
        __syncwarp();   // warp done reading buffer bj before refill

        if (++bj >= PIPE) bj = 0;
    }

    // ---- epilogue ----
    const int c  = c0 + cap;
    const int o0 = to * 8;
    const float4* bias4 = (const float4*)(bias + (size_t)c * OO + o0);
    const float4 bz0 = bias4[0];
    const float4 bz1 = bias4[1];

    #pragma unroll
    for (int k = 0; k < 4; ++k) {
        float v0, v1, v2, v3, v4, v5, v6, v7;
        unpack2(acc[k][0], v0, v1);
        unpack2(acc[k][1], v2, v3);
        unpack2(acc[k][2], v4, v5);
        unpack2(acc[k][3], v6, v7);

        float4 lo = make_float4(v0 + bz0.x, v1 + bz0.y, v2 + bz0.z, v3 + bz0.w);
        float4 hi = make_float4(v4 + bz1.x, v5 + bz1.y, v6 + bz1.z, v7 + bz1.w);

        const int b = b0 + tb + 8 * k;
        float* op = out + ((size_t)b * CC + c) * OO + o0;
        *(float4*)(op)     = lo;
        *(float4*)(op + 4) = hi;
    }
}

extern "C" void kernel_launch(void* const* d_in, const int* in_sizes, int n_in,
                              void* d_out, int out_size)
{
    (void)in_sizes; (void)n_in; (void)out_size;
    const float* x    = (const float*)d_in[0];
    const float* W    = (const float*)d_in[1];
    const float* bias = (const float*)d_in[2];
    float*       out  = (float*)d_out;

    const int smem_bytes = SMEM_FLOATS * sizeof(float);   // 72 KB
    static bool attr_done = false;
    if (!attr_done) {
        cudaFuncSetAttribute(primarycaps_kernel,
                             cudaFuncAttributeMaxDynamicSharedMemorySize,
                             smem_bytes);
        attr_done = true;
    }
    dim3 grid(CC / CAPS_CTA, BB / BH);   // (512, 2); b-half is slow axis
    primarycaps_kernel<<<grid, NTH, smem_bytes>>>(x, W, bias, out);
}

// round 11
// speedup vs baseline: 1.3104x; 1.3104x over previous
#include <cuda_runtime.h>
#include <cstdint>

#define BB 64
#define CC 4096
#define IND 512
#define OO 16
#define TI 32                 // i-tile: full 128B per (b,c) row
#define NTILES (IND / TI)     // 16
#define NCAPW 2               // capsules per WARP
#define WARPS 4
#define NTH (32 * WARPS)
#define CAPS_CTA (NCAPW * WARPS)   // 8
#define BH 32                 // b-rows per CTA (page-set split, proven R9)
#define PIPE 2

#define XCAP 1024             // 32 rows x 32 words per capsule per stage
#define WCAP 512              // 32 i-rows x 16 words per capsule per stage
#define XWARP (NCAPW * XCAP)  // 2048 floats
#define WWARP (NCAPW * WCAP)  // 1024 floats
#define STG (XWARP + WWARP)   // 3072 floats = 12 KB per warp-stage
#define SMEM_FLOATS (PIPE * WARPS * STG)   // 24576 floats = 96 KB

// ---- packed f32x2 helpers ----
__device__ __forceinline__ uint64_t pack_dup(float x) {
    uint64_t r;
    asm("mov.b64 %0, {%1, %1};" : "=l"(r) : "f"(x));
    return r;
}
__device__ __forceinline__ void fma2(uint64_t& d, uint64_t a, uint64_t b) {
    asm("fma.rn.f32x2 %0, %1, %2, %0;" : "+l"(d) : "l"(a), "l"(b));
}
__device__ __forceinline__ void unpack2(uint64_t v, float& lo, float& hi) {
    asm("mov.b64 {%0, %1}, %2;" : "=f"(lo), "=f"(hi) : "l"(v));
}

// ---- cp.async 16B, L1-bypass ----
__device__ __forceinline__ void cp16(void* dst_smem, const void* src) {
    uint32_t d = (uint32_t)__cvta_generic_to_shared(dst_smem);
    asm volatile("cp.async.cg.shared.global [%0], [%1], 16;"
                 :: "r"(d), "l"(src) : "memory");
}
__device__ __forceinline__ void cp_commit() {
    asm volatile("cp.async.commit_group;" ::: "memory");
}
__device__ __forceinline__ void cp_wait1() {
    asm volatile("cp.async.wait_group 1;" ::: "memory");
}
__device__ __forceinline__ void cp_wait0() {
    asm volatile("cp.async.wait_group 0;" ::: "memory");
}

extern __shared__ float sm[];

__global__ __launch_bounds__(NTH)
void primarycaps_kernel(const float* __restrict__ x,
                        const float* __restrict__ W,
                        const float* __restrict__ bias,
                        float* __restrict__ out)
{
    const int t    = threadIdx.x;
    const int wid  = t >> 5;
    const int lane = t & 31;

    const int c0 = blockIdx.x * CAPS_CTA + wid * NCAPW;  // this warp's 2 caps
    const int b0 = blockIdx.y * BH;                      // this CTA's b-half

    // compute map (within warp)
    const int tb  = lane & 7;         // b-group: owns rows tb + 8k (k=0..3)
    const int to  = (lane >> 3) & 1;  // o-half
    const int cap = lane >> 4;        // capsule within warp

    // x staging map: one instr = 4 full 128B lines (4 rows x 8 chunks)
    const int srow = lane >> 3;       // local row 0..3 within group of 4
    const int sch  = lane & 7;        // 16B chunk 0..7 within 128B row

    // per-warp smem stage bases
    float* const stg0 = sm + (0 * WARPS + wid) * STG;
    float* const stg1 = sm + (1 * WARPS + wid) * STG;

    // ---- accumulators: 4 b-rows x 4 o-pairs (packed f32x2) ----
    uint64_t acc[4][4];
    #pragma unroll
    for (int k = 0; k < 4; ++k)
        #pragma unroll
        for (int j = 0; j < 4; ++j)
            acc[k][j] = 0ULL;

    // ---- stage helper: tile jt into buffer bf (this warp only) ----
    auto stage = [&](int bf, int jt) {
        float* dx = bf ? stg1 : stg0;          // x at +0, W at +XWARP
        // x: 2 caps x 8 row-groups; each instr = 4 rows x 128B (full lines)
        #pragma unroll
        for (int cc = 0; cc < NCAPW; ++cc) {
            #pragma unroll
            for (int g = 0; g < 8; ++g) {
                const int row = g * 4 + srow;          // 0..31
                cp16(&dx[cc * XCAP + row * 32 + ((sch ^ (row & 7)) * 4)],
                     x + ((size_t)(b0 + row) * CC + c0 + cc) * IND
                       + (size_t)jt * TI + sch * 4);
            }
        }
        // W: 2 caps x 4 chunks of 512B contiguous (full 2KB tile per capsule)
        float* dw = (bf ? stg1 : stg0) + XWARP;
        #pragma unroll
        for (int cc = 0; cc < NCAPW; ++cc) {
            #pragma unroll
            for (int m = 0; m < 4; ++m) {
                const int ofs = m * 128 + lane * 4;    // floats within 2KB tile
                cp16(&dw[cc * WCAP + ofs],
                     W + ((size_t)(c0 + cc) * IND + (size_t)jt * TI) * OO + ofs);
            }
        }
        cp_commit();
    };

    // ---- prologue ----
    stage(0, 0);

    for (int j = 0; j < NTILES; ++j) {
        // issue next stage first (overlap), then wait for tile j
        if (j + 1 < NTILES) {
            stage((j + 1) & 1, j + 1);
            cp_wait1();
        } else {
            cp_wait0();
        }
        __syncwarp();

        // ---- compute tile j ----
        const float* __restrict__ xb = ((j & 1) ? stg1 : stg0) + cap * XCAP;
        const float* __restrict__ wb = ((j & 1) ? stg1 : stg0) + XWARP + cap * WCAP;

        #pragma unroll
        for (int q = 0; q < 8; ++q) {           // 8 chunks of 4 i
            float4 xv[4];
            #pragma unroll
            for (int k = 0; k < 4; ++k) {
                const int row = tb + 8 * k;
                xv[k] = *(const float4*)&xb[row * 32 + ((q ^ (row & 7)) * 4)];
            }

            #pragma unroll
            for (int r = 0; r < 4; ++r) {
                const int i = q * 4 + r;
                const ulonglong2 wA =
                    *(const ulonglong2*)&wb[i * OO + to * 8];
                const ulonglong2 wB =
                    *(const ulonglong2*)&wb[i * OO + to * 8 + 4];

                #pragma unroll
                for (int k = 0; k < 4; ++k) {
                    const float xs = (r == 0) ? xv[k].x :
                                     (r == 1) ? xv[k].y :
                                     (r == 2) ? xv[k].z : xv[k].w;
                    const uint64_t xd = pack_dup(xs);
                    fma2(acc[k][0], xd, wA.x);
                    fma2(acc[k][1], xd, wA.y);
                    fma2(acc[k][2], xd, wB.x);
                    fma2(acc[k][3], xd, wB.y);
                }
            }
        }
        __syncwarp();   // warp done reading buffer before it is refilled
    }

    // ---- epilogue ----
    const int c  = c0 + cap;
    const int o0 = to * 8;
    const float4* bias4 = (const float4*)(bias + (size_t)c * OO + o0);
    const float4 bz0 = bias4[0];
    const float4 bz1 = bias4[1];

    #pragma unroll
    for (int k = 0; k < 4; ++k) {
        float v0, v1, v2, v3, v4, v5, v6, v7;
        unpack2(acc[k][0], v0, v1);
        unpack2(acc[k][1], v2, v3);
        unpack2(acc[k][2], v4, v5);
        unpack2(acc[k][3], v6, v7);

        float4 lo = make_float4(v0 + bz0.x, v1 + bz0.y, v2 + bz0.z, v3 + bz0.w);
        float4 hi = make_float4(v4 + bz1.x, v5 + bz1.y, v6 + bz1.z, v7 + bz1.w);

        const int b = b0 + tb + 8 * k;
        float* op = out + ((size_t)b * CC + c) * OO + o0;
        *(float4*)(op)     = lo;
        *(float4*)(op + 4) = hi;
    }
}

extern "C" void kernel_launch(void* const* d_in, const int* in_sizes, int n_in,
                              void* d_out, int out_size)
{
    (void)in_sizes; (void)n_in; (void)out_size;
    const float* x    = (const float*)d_in[0];
    const float* W    = (const float*)d_in[1];
    const float* bias = (const float*)d_in[2];
    float*       out  = (float*)d_out;

    const int smem_bytes = SMEM_FLOATS * sizeof(float);   // 96 KB
    static bool attr_done = false;
    if (!attr_done) {
        cudaFuncSetAttribute(primarycaps_kernel,
                             cudaFuncAttributeMaxDynamicSharedMemorySize,
                             smem_bytes);
        attr_done = true;
    }
    dim3 grid(CC / CAPS_CTA, BB / BH);   // (512, 2)
    primarycaps_kernel<<<grid, NTH, smem_bytes>>>(x, W, bias, out);
}

// round 12
// speedup vs baseline: 1.4766x; 1.1268x over previous
#include <cuda_runtime.h>
#include <cstdint>

#define BB 64
#define CC 4096
#define IND 512
#define OO 16
#define TI 32                 // i-tile: full 128B per (b,c) row
#define NTILES (IND / TI)     // 16
#define NCAPW 2               // capsules per WARP
#define WARPS 4
#define NTH (32 * WARPS)
#define CAPS_CTA (NCAPW * WARPS)   // 8
#define BH 32                 // b-rows per CTA (page-set split, proven R9)
#define PIPE 2

#define XCAP 1024             // 32 rows x 32 words per capsule per stage
#define WCAP 512              // 32 i-rows x 16 words per capsule per stage
#define XWARP (NCAPW * XCAP)  // 2048 floats
#define WWARP (NCAPW * WCAP)  // 1024 floats
#define STG (XWARP + WWARP)   // 3072 floats = 12 KB per warp-stage
#define SMEM_FLOATS (PIPE * WARPS * STG)   // 24576 floats = 96 KB

// ---- packed f32x2 helpers ----
__device__ __forceinline__ uint64_t pack_dup(float x) {
    uint64_t r;
    asm("mov.b64 %0, {%1, %1};" : "=l"(r) : "f"(x));
    return r;
}
__device__ __forceinline__ void fma2(uint64_t& d, uint64_t a, uint64_t b) {
    asm("fma.rn.f32x2 %0, %1, %2, %0;" : "+l"(d) : "l"(a), "l"(b));
}
__device__ __forceinline__ void unpack2(uint64_t v, float& lo, float& hi) {
    asm("mov.b64 {%0, %1}, %2;" : "=f"(lo), "=f"(hi) : "l"(v));
}

// ---- cp.async 16B, L1-bypass ----
__device__ __forceinline__ void cp16(void* dst_smem, const void* src) {
    uint32_t d = (uint32_t)__cvta_generic_to_shared(dst_smem);
    asm volatile("cp.async.cg.shared.global [%0], [%1], 16;"
                 :: "r"(d), "l"(src) : "memory");
}
__device__ __forceinline__ void cp_commit() {
    asm volatile("cp.async.commit_group;" ::: "memory");
}
__device__ __forceinline__ void cp_wait1() {
    asm volatile("cp.async.wait_group 1;" ::: "memory");
}
__device__ __forceinline__ void cp_wait0() {
    asm volatile("cp.async.wait_group 0;" ::: "memory");
}

extern __shared__ float sm[];

__global__ __launch_bounds__(NTH)
void primarycaps_kernel(const float* __restrict__ x,
                        const float* __restrict__ W,
                        const float* __restrict__ bias,
                        float* __restrict__ out)
{
    const int t    = threadIdx.x;
    const int wid  = t >> 5;
    const int lane = t & 31;

    // PAIR-ADJACENT SCHEDULING: blockIdx.x = b-half (fast axis) so the two
    // CTAs sharing W[c0..c0+7] are linear neighbors -> same wave -> L2 reuse.
    const int c0 = blockIdx.y * CAPS_CTA + wid * NCAPW;  // this warp's 2 caps
    const int b0 = blockIdx.x * BH;                      // this CTA's b-half

    // compute map (within warp)
    const int tb  = lane & 7;         // b-group: owns rows tb + 8k (k=0..3)
    const int to  = (lane >> 3) & 1;  // o-half
    const int cap = lane >> 4;        // capsule within warp

    // x staging map: one instr = 4 full 128B lines (4 rows x 8 chunks)
    const int srow = lane >> 3;       // local row 0..3 within group of 4
    const int sch  = lane & 7;        // 16B chunk 0..7 within 128B row

    // per-warp smem stage bases
    float* const stg0 = sm + (0 * WARPS + wid) * STG;
    float* const stg1 = sm + (1 * WARPS + wid) * STG;

    // ---- accumulators: 4 b-rows x 4 o-pairs (packed f32x2) ----
    uint64_t acc[4][4];
    #pragma unroll
    for (int k = 0; k < 4; ++k)
        #pragma unroll
        for (int j = 0; j < 4; ++j)
            acc[k][j] = 0ULL;

    // ---- stage helper: tile jt into buffer bf (this warp only) ----
    auto stage = [&](int bf, int jt) {
        float* dx = bf ? stg1 : stg0;          // x at +0, W at +XWARP
        // x: 2 caps x 8 row-groups; each instr = 4 rows x 128B (full lines)
        #pragma unroll
        for (int cc = 0; cc < NCAPW; ++cc) {
            #pragma unroll
            for (int g = 0; g < 8; ++g) {
                const int row = g * 4 + srow;          // 0..31
                cp16(&dx[cc * XCAP + row * 32 + ((sch ^ (row & 7)) * 4)],
                     x + ((size_t)(b0 + row) * CC + c0 + cc) * IND
                       + (size_t)jt * TI + sch * 4);
            }
        }
        // W: 2 caps x 4 chunks of 512B contiguous (full 2KB tile per capsule)
        float* dw = (bf ? stg1 : stg0) + XWARP;
        #pragma unroll
        for (int cc = 0; cc < NCAPW; ++cc) {
            #pragma unroll
            for (int m = 0; m < 4; ++m) {
                const int ofs = m * 128 + lane * 4;    // floats within 2KB tile
                cp16(&dw[cc * WCAP + ofs],
                     W + ((size_t)(c0 + cc) * IND + (size_t)jt * TI) * OO + ofs);
            }
        }
        cp_commit();
    };

    // ---- prologue ----
    stage(0, 0);

    for (int j = 0; j < NTILES; ++j) {
        // issue next stage first (overlap), then wait for tile j
        if (j + 1 < NTILES) {
            stage((j + 1) & 1, j + 1);
            cp_wait1();
        } else {
            cp_wait0();
        }
        __syncwarp();

        // ---- compute tile j ----
        const float* __restrict__ xb = ((j & 1) ? stg1 : stg0) + cap * XCAP;
        const float* __restrict__ wb = ((j & 1) ? stg1 : stg0) + XWARP + cap * WCAP;

        #pragma unroll
        for (int q = 0; q < 8; ++q) {           // 8 chunks of 4 i
            float4 xv[4];
            #pragma unroll
            for (int k = 0; k < 4; ++k) {
                const int row = tb + 8 * k;
                xv[k] = *(const float4*)&xb[row * 32 + ((q ^ (row & 7)) * 4)];
            }

            #pragma unroll
            for (int r = 0; r < 4; ++r) {
                const int i = q * 4 + r;
                const ulonglong2 wA =
                    *(const ulonglong2*)&wb[i * OO + to * 8];
                const ulonglong2 wB =
                    *(const ulonglong2*)&wb[i * OO + to * 8 + 4];

                #pragma unroll
                for (int k = 0; k < 4; ++k) {
                    const float xs = (r == 0) ? xv[k].x :
                                     (r == 1) ? xv[k].y :
                                     (r == 2) ? xv[k].z : xv[k].w;
                    const uint64_t xd = pack_dup(xs);
                    fma2(acc[k][0], xd, wA.x);
                    fma2(acc[k][1], xd, wA.y);
                    fma2(acc[k][2], xd, wB.x);
                    fma2(acc[k][3], xd, wB.y);
                }
            }
        }
        __syncwarp();   // warp done reading buffer before it is refilled
    }

    // ---- epilogue ----
    const int c  = c0 + cap;
    const int o0 = to * 8;
    const float4* bias4 = (const float4*)(bias + (size_t)c * OO + o0);
    const float4 bz0 = bias4[0];
    const float4 bz1 = bias4[1];

    #pragma unroll
    for (int k = 0; k < 4; ++k) {
        float v0, v1, v2, v3, v4, v5, v6, v7;
        unpack2(acc[k][0], v0, v1);
        unpack2(acc[k][1], v2, v3);
        unpack2(acc[k][2], v4, v5);
        unpack2(acc[k][3], v6, v7);

        float4 lo = make_float4(v0 + bz0.x, v1 + bz0.y, v2 + bz0.z, v3 + bz0.w);
        float4 hi = make_float4(v4 + bz1.x, v5 + bz1.y, v6 + bz1.z, v7 + bz1.w);

        const int b = b0 + tb + 8 * k;
        float* op = out + ((size_t)b * CC + c) * OO + o0;
        *(float4*)(op)     = lo;
        *(float4*)(op + 4) = hi;
    }
}

extern "C" void kernel_launch(void* const* d_in, const int* in_sizes, int n_in,
                              void* d_out, int out_size)
{
    (void)in_sizes; (void)n_in; (void)out_size;
    const float* x    = (const float*)d_in[0];
    const float* W    = (const float*)d_in[1];
    const float* bias = (const float*)d_in[2];
    float*       out  = (float*)d_out;

    const int smem_bytes = SMEM_FLOATS * sizeof(float);   // 96 KB
    static bool attr_done = false;
    if (!attr_done) {
        cudaFuncSetAttribute(primarycaps_kernel,
                             cudaFuncAttributeMaxDynamicSharedMemorySize,
                             smem_bytes);
        attr_done = true;
    }
    dim3 grid(BB / BH, CC / CAPS_CTA);   // (2, 512): b-half is the FAST axis
    primarycaps_kernel<<<grid, NTH, smem_bytes>>>(x, W, bias, out);
}